// round 5
// baseline (speedup 1.0000x reference)
#include <cuda_runtime.h>
#include <math.h>

#define EMBD 1024
#define CIND 512
#define BATCH 8
#define NTOK 1024
#define SEQL 1024

// Scratch (allocation-free rule: __device__ globals). Feature-major (E x tokens) per batch.
__device__ float g_xt[BATCH * EMBD * NTOK];  // proj_in result
__device__ float g_Q [BATCH * EMBD * NTOK];
__device__ float g_Kf[BATCH * EMBD * SEQL];
__device__ float g_Vf[BATCH * EMBD * SEQL];
__device__ float g_S [BATCH * NTOK * SEQL]; // raw scores
__device__ float g_O [BATCH * EMBD * NTOK]; // att @ V (feature-major)

// ---- packed f32x2 helpers (sm_103a FFMA2 path; exact fp32 arithmetic) ------
__device__ __forceinline__ unsigned long long pack_bcast2(float x) {
    unsigned long long r;
    asm("mov.b64 %0, {%1, %1};" : "=l"(r) : "f"(x));
    return r;
}
__device__ __forceinline__ void fma2(unsigned long long& d,
                                     unsigned long long a,
                                     unsigned long long b) {
    asm("fma.rn.f32x2 %0, %1, %2, %0;" : "+l"(d) : "l"(a), "l"(b));
}
__device__ __forceinline__ float2 unpack2(unsigned long long v) {
    float2 f;
    asm("mov.b64 {%0, %1}, %2;" : "=f"(f.x), "=f"(f.y) : "l"(v));
    return f;
}

// ---------------------------------------------------------------------------
// Batched tiled SGEMM: C[m][n] = alpha * sum_k Aop[m][k]*Bop[k][n] + bias[m]
//   AT: A stored (K x M) row-major (so Aop[m][k] = A[k*lda + m])
//   BT: B stored (N x K) row-major (so Bop[k][n] = B[n*ldb + k])
// Tile 128x128, BK=16, 256 threads, 8x8 microtile, double-buffered smem with
// register prefetch. Inner product uses packed fma.rn.f32x2 (pairs along n):
// B pairs are adjacent floats in smem -> loaded directly as u64 lanes.
//
// Slot mapping (8 slots/thread, idx = i*256+tid covers [0,2048) = 16 kk x 128):
//   AT : kk=idx>>7, col=idx&127 : smem[kk][col] <- A[(k0+kk)*lda + m0+col]
//   A  : kk=idx&15, col=idx>>4  : smem[kk][col] <- A[(m0+col)*lda + k0+kk]
//   BT : kk=idx&15, col=idx>>4  : smem[kk][col] <- B[(n0+col)*ldb + k0+kk]
//   B  : kk=idx>>7, col=idx&127 : smem[kk][col] <- B[(k0+kk)*ldb + n0+col]
// ---------------------------------------------------------------------------
template <bool AT, bool BT>
__global__ __launch_bounds__(256) void sgemm128(
    const float* __restrict__ A, const float* __restrict__ B,
    float* __restrict__ C, const float* __restrict__ bias,
    int M, int N, int K, int lda, int ldb, int ldc,
    long sA, long sB, long sC, float alpha)
{
    __shared__ float As[2][16][128];
    __shared__ float Bs[2][16][128];

    const int tid = threadIdx.x;
    A += (long)blockIdx.z * sA;
    B += (long)blockIdx.z * sB;
    C += (long)blockIdx.z * sC;
    const int n0 = blockIdx.x * 128;
    const int m0 = blockIdx.y * 128;
    const int tx = tid & 15;   // n direction
    const int ty = tid >> 4;   // m direction

    const float* pA[8];
    const float* pB[8];
    int sa[8], sb[8];
    const long aStep = AT ? (long)lda : 1L;
    const long bStep = BT ? 1L : (long)ldb;
#pragma unroll
    for (int i = 0; i < 8; i++) {
        const int idx = i * 256 + tid;
        if (AT) {
            sa[i] = (idx >> 7) * 128 + (idx & 127);
            pA[i] = A + (long)(idx >> 7) * lda + m0 + (idx & 127);
        } else {
            sa[i] = (idx & 15) * 128 + (idx >> 4);
            pA[i] = A + (long)(m0 + (idx >> 4)) * lda + (idx & 15);
        }
        if (BT) {
            sb[i] = (idx & 15) * 128 + (idx >> 4);
            pB[i] = B + (long)(n0 + (idx >> 4)) * ldb + (idx & 15);
        } else {
            sb[i] = (idx >> 7) * 128 + (idx & 127);
            pB[i] = B + (long)(idx >> 7) * ldb + n0 + (idx & 127);
        }
    }

    // 8x8 fp32 microtile held as 8x4 packed f32x2 (pairs along n).
    unsigned long long acc[8][4];
#pragma unroll
    for (int i = 0; i < 8; i++)
#pragma unroll
        for (int j = 0; j < 4; j++) acc[i][j] = 0ULL;

    // Preload tile 0 into buffer 0.
    {
        float* as0 = &As[0][0][0];
        float* bs0 = &Bs[0][0][0];
#pragma unroll
        for (int i = 0; i < 8; i++) {
            as0[sa[i]] = pA[i][0];
            bs0[sb[i]] = pB[i][0];
        }
    }
    __syncthreads();

    int buf = 0;
    for (int k0 = 0; k0 < K; k0 += 16) {
        const bool has_next = (k0 + 16 < K);
        float ra[8], rb[8];
        if (has_next) {
            const long ao = (long)(k0 + 16) * aStep;
            const long bo = (long)(k0 + 16) * bStep;
#pragma unroll
            for (int i = 0; i < 8; i++) {
                ra[i] = pA[i][ao];
                rb[i] = pB[i][bo];
            }
        }

        const float* as = &As[buf][0][0];
        const float* bs = &Bs[buf][0][0];
#pragma unroll
        for (int kk = 0; kk < 16; kk++) {
            // B pairs: 8 floats = 4 u64 lanes, two LDS.128.
            const ulonglong2 bq0 = *(const ulonglong2*)(bs + kk * 128 + tx * 8);
            const ulonglong2 bq1 = *(const ulonglong2*)(bs + kk * 128 + tx * 8 + 4);
            const unsigned long long bp[4] = {bq0.x, bq0.y, bq1.x, bq1.y};
            // A values: 8 floats, broadcast-packed {a,a} (hoisted before FMAs).
            const float4 a0 = *(const float4*)(as + kk * 128 + ty * 8);
            const float4 a1 = *(const float4*)(as + kk * 128 + ty * 8 + 4);
            const float av[8] = {a0.x, a0.y, a0.z, a0.w, a1.x, a1.y, a1.z, a1.w};
            unsigned long long ap[8];
#pragma unroll
            for (int i = 0; i < 8; i++) ap[i] = pack_bcast2(av[i]);
#pragma unroll
            for (int i = 0; i < 8; i++)
#pragma unroll
                for (int j = 0; j < 4; j++)
                    fma2(acc[i][j], ap[i], bp[j]);
        }

        if (has_next) {
            float* asn = &As[buf ^ 1][0][0];
            float* bsn = &Bs[buf ^ 1][0][0];
#pragma unroll
            for (int i = 0; i < 8; i++) {
                asn[sa[i]] = ra[i];
                bsn[sb[i]] = rb[i];
            }
        }
        __syncthreads();
        buf ^= 1;
    }

#pragma unroll
    for (int i = 0; i < 8; i++) {
        const int m = m0 + ty * 8 + i;
        const float bv = bias ? bias[m] : 0.f;
        float* crow = C + (long)m * ldc + n0 + tx * 8;
        const float2 v0 = unpack2(acc[i][0]);
        const float2 v1 = unpack2(acc[i][1]);
        const float2 v2 = unpack2(acc[i][2]);
        const float2 v3 = unpack2(acc[i][3]);
        float4 c0, c1;
        c0.x = alpha * v0.x + bv;
        c0.y = alpha * v0.y + bv;
        c0.z = alpha * v1.x + bv;
        c0.w = alpha * v1.y + bv;
        c1.x = alpha * v2.x + bv;
        c1.y = alpha * v2.y + bv;
        c1.z = alpha * v3.x + bv;
        c1.w = alpha * v3.y + bv;
        *(float4*)(crow) = c0;
        *(float4*)(crow + 4) = c1;
    }
}

// ---------------------------------------------------------------------------
// Masked row softmax: one block per (b, i) row of length SEQL.
//   att[row][j] = softmax_j( mask ? -1e9 : S[row][j] )
// ---------------------------------------------------------------------------
__global__ __launch_bounds__(256) void softmax_rows(
    const float* __restrict__ S, const unsigned char* __restrict__ mask,
    float* __restrict__ att)
{
    __shared__ float red[256];
    const long row = blockIdx.x;
    const float* s = S + row * SEQL;
    const unsigned char* m = mask + row * SEQL;
    float* o = att + row * SEQL;
    const int t = threadIdx.x;

    float v[4];
    float lm = -3.4e38f;
#pragma unroll
    for (int i = 0; i < 4; i++) {
        int j = t + i * 256;
        v[i] = m[j] ? -1e9f : s[j];
        lm = fmaxf(lm, v[i]);
    }
    red[t] = lm;
    __syncthreads();
    for (int off = 128; off > 0; off >>= 1) {
        if (t < off) red[t] = fmaxf(red[t], red[t + off]);
        __syncthreads();
    }
    const float mx = red[0];
    __syncthreads();

    float ls = 0.f;
#pragma unroll
    for (int i = 0; i < 4; i++) {
        v[i] = __expf(v[i] - mx);
        ls += v[i];
    }
    red[t] = ls;
    __syncthreads();
    for (int off = 128; off > 0; off >>= 1) {
        if (t < off) red[t] += red[t + off];
        __syncthreads();
    }
    const float inv = 1.f / red[0];
#pragma unroll
    for (int i = 0; i < 4; i++) o[t + i * 256] = v[i] * inv;
}

// ---------------------------------------------------------------------------
// Launch
// ---------------------------------------------------------------------------
extern "C" void kernel_launch(void* const* d_in, const int* in_sizes, int n_in,
                              void* d_out, int out_size)
{
    const float* x        = (const float*)d_in[0];          // (8,512,32,32)
    const float* content  = (const float*)d_in[1];          // (8,1024,1024)
    const unsigned char* pmask = (const unsigned char*)d_in[2]; // (8,1024,1024) bool
    const float* W_in     = (const float*)d_in[3];          // (1024,512)
    const float* b_in     = (const float*)d_in[4];          // (1024)
    const float* Wq       = (const float*)d_in[5];          // (1024,1024)
    const float* Wk       = (const float*)d_in[6];
    const float* Wv       = (const float*)d_in[7];
    const float* W_out    = (const float*)d_in[8];          // (512,1024)
    const float* b_out    = (const float*)d_in[9];          // (512)

    float* out = (float*)d_out;                             // (8,512,32,32)
    float* att = out + (long)BATCH * CIND * NTOK;           // (8,1024,1024)

    float *xt, *Qp, *Kp, *Vp, *Sp, *Op;
    cudaGetSymbolAddress((void**)&xt, g_xt);
    cudaGetSymbolAddress((void**)&Qp, g_Q);
    cudaGetSymbolAddress((void**)&Kp, g_Kf);
    cudaGetSymbolAddress((void**)&Vp, g_Vf);
    cudaGetSymbolAddress((void**)&Sp, g_S);
    cudaGetSymbolAddress((void**)&Op, g_O);

    const dim3 blk(256);
    const dim3 gEE(NTOK / 128, EMBD / 128, BATCH);  // (8,8,8)
    const dim3 gCN(NTOK / 128, CIND / 128, BATCH);  // (8,4,8)

    // 1) xt[e][n] = sum_c W_in[e][c] * x[b][c][n] + b_in[e]           (NN)
    sgemm128<false, false><<<gEE, blk>>>(
        W_in, x, xt, b_in, EMBD, NTOK, CIND,
        CIND, NTOK, NTOK, 0L, (long)CIND * NTOK, (long)EMBD * NTOK, 1.f);

    // 2) Q[e'][n] = sum_e Wq[e'][e] * xt[e][n]                        (NN)
    sgemm128<false, false><<<gEE, blk>>>(
        Wq, xt, Qp, nullptr, EMBD, NTOK, EMBD,
        EMBD, NTOK, NTOK, 0L, (long)EMBD * NTOK, (long)EMBD * NTOK, 1.f);

    // 3) K[e'][s] = sum_d Wk[e'][d] * content[b][s][d]                (NT)
    sgemm128<false, true><<<gEE, blk>>>(
        Wk, content, Kp, nullptr, EMBD, SEQL, EMBD,
        EMBD, EMBD, SEQL, 0L, (long)SEQL * EMBD, (long)EMBD * SEQL, 1.f);

    // 4) V[e'][s]                                                      (NT)
    sgemm128<false, true><<<gEE, blk>>>(
        Wv, content, Vp, nullptr, EMBD, SEQL, EMBD,
        EMBD, EMBD, SEQL, 0L, (long)SEQL * EMBD, (long)EMBD * SEQL, 1.f);

    // 5) S[i][j] = scale * sum_d Q[d][i] * K[d][j]                    (TN)
    sgemm128<true, false><<<dim3(SEQL / 128, NTOK / 128, BATCH), blk>>>(
        Qp, Kp, Sp, nullptr, NTOK, SEQL, EMBD,
        NTOK, SEQL, SEQL, (long)EMBD * NTOK, (long)EMBD * SEQL,
        (long)NTOK * SEQL, 0.03125f /* EMB^-0.5 */);

    // 6) att = softmax(mask ? -1e9 : S)  -> written directly to output
    softmax_rows<<<BATCH * NTOK, 256>>>(Sp, pmask, att);

    // 7) O[d][i] = sum_j V[d][j] * att[i][j]                          (NT)
    sgemm128<false, true><<<gEE, blk>>>(
        Vp, att, Op, nullptr, EMBD, NTOK, SEQL,
        SEQL, SEQL, NTOK, (long)EMBD * SEQL, (long)NTOK * SEQL,
        (long)EMBD * NTOK, 1.f);

    // 8) out[c][n] = sum_e W_out[c][e] * O[e][n] + b_out[c]           (NN)
    sgemm128<false, false><<<gCN, blk>>>(
        W_out, Op, out, b_out, CIND, NTOK, EMBD,
        EMBD, NTOK, NTOK, 0L, (long)EMBD * NTOK, (long)CIND * NTOK, 1.f);
}

// round 13
// speedup vs baseline: 2.9449x; 2.9449x over previous
#include <cuda_runtime.h>
#include <cuda_bf16.h>

#define EMBD 1024
#define CIND 512
#define BATCH 8
#define NTOK 1024
#define SEQL 1024

typedef __nv_bfloat16 bf16;
typedef unsigned int u32;

// ---------------------------------------------------------------------------
// Scratch (__device__ globals; allocation-free rule)
// ---------------------------------------------------------------------------
__device__ bf16 g_XThi[(long)BATCH * NTOK * CIND];   // x transposed (b,n,c)
__device__ bf16 g_XTlo[(long)BATCH * NTOK * CIND];
__device__ bf16 g_CThi[(long)BATCH * SEQL * EMBD];   // content (b,s,e)
__device__ bf16 g_CTlo[(long)BATCH * SEQL * EMBD];
__device__ bf16 g_WIhi[EMBD * CIND];
__device__ bf16 g_WIlo[EMBD * CIND];
__device__ bf16 g_WQhi[EMBD * EMBD];
__device__ bf16 g_WQlo[EMBD * EMBD];
__device__ bf16 g_WKhi[EMBD * EMBD];
__device__ bf16 g_WKlo[EMBD * EMBD];
__device__ bf16 g_WVhi[EMBD * EMBD];
__device__ bf16 g_WVlo[EMBD * EMBD];
__device__ bf16 g_WOhi[CIND * EMBD];
__device__ bf16 g_WOlo[CIND * EMBD];
__device__ bf16 g_XPhi[(long)BATCH * NTOK * EMBD];   // proj_in out (tokens x e)
__device__ bf16 g_XPlo[(long)BATCH * NTOK * EMBD];
__device__ bf16 g_Qhi [(long)BATCH * NTOK * EMBD];
__device__ bf16 g_Qlo [(long)BATCH * NTOK * EMBD];
__device__ bf16 g_Khi [(long)BATCH * SEQL * EMBD];
__device__ bf16 g_Klo [(long)BATCH * SEQL * EMBD];
__device__ bf16 g_VThi[(long)BATCH * EMBD * SEQL];   // V^T (d x s)
__device__ bf16 g_VTlo[(long)BATCH * EMBD * SEQL];
__device__ bf16 g_AThi[(long)BATCH * NTOK * SEQL];   // att hi/lo
__device__ bf16 g_ATlo[(long)BATCH * NTOK * SEQL];
__device__ bf16 g_AOhi[(long)BATCH * NTOK * EMBD];   // att@V (tokens x d)
__device__ bf16 g_AOlo[(long)BATCH * NTOK * EMBD];
__device__ float g_S [(long)BATCH * NTOK * SEQL];    // raw scores fp32

// ---------------------------------------------------------------------------
// Baseline-ISA tensor ops: ldmatrix + mma.sync (no 'a'-target features)
// ---------------------------------------------------------------------------
__device__ __forceinline__ u32 smem_u32(const void* p) {
    u32 a;
    asm("{ .reg .u64 t; cvta.to.shared.u64 t, %1; cvt.u32.u64 %0, t; }"
        : "=r"(a) : "l"(p));
    return a;
}
__device__ __forceinline__ void ldsm4(u32& r0, u32& r1, u32& r2, u32& r3, u32 a) {
    asm volatile("ldmatrix.sync.aligned.m8n8.x4.shared.b16 {%0,%1,%2,%3}, [%4];"
                 : "=r"(r0), "=r"(r1), "=r"(r2), "=r"(r3) : "r"(a));
}
__device__ __forceinline__ void mma16816(float* c, const u32* a, const u32* b) {
    asm volatile(
        "mma.sync.aligned.m16n8k16.row.col.f32.bf16.bf16.f32 "
        "{%0,%1,%2,%3}, {%4,%5,%6,%7}, {%8,%9}, {%0,%1,%2,%3};"
        : "+f"(c[0]), "+f"(c[1]), "+f"(c[2]), "+f"(c[3])
        : "r"(a[0]), "r"(a[1]), "r"(a[2]), "r"(a[3]), "r"(b[0]), "r"(b[1]));
}

// ---------------------------------------------------------------------------
// Split-precision bf16 GEMM via mma.sync.
// D[m][n] = alpha * sum_k (Ahi+Alo)[m][k]*(Bhi+Blo)[n][k] (+bias_row/+bias_col)
// (AloBlo term dropped: ~2^-16 relative, far below 1e-3 gate)
// A: [Mtot][Ktot] row-major bf16, B: [Ntot][Ktot] row-major bf16.
// CTA tile 128x64, 8 warps (4 along M, 2 along N), warp tile 32x32, KC=32.
// Smem row stride 40 bf16 (80 B) -> conflict-free ldmatrix phases.
// ---------------------------------------------------------------------------
#define BM 128
#define BN 64
#define KC 32
#define KSTR 40
#define SM_AHI 0
#define SM_ALO (BM * KSTR)                       // 5120
#define SM_BHI (2 * BM * KSTR)                   // 10240
#define SM_BLO (2 * BM * KSTR + BN * KSTR)       // 12800
#define SM_TOT (2 * BM * KSTR + 2 * BN * KSTR)   // 15360 bf16 = 30 KB

__global__ void __launch_bounds__(256) mma_gemm(
    const bf16* __restrict__ Ahi, const bf16* __restrict__ Alo,
    const bf16* __restrict__ Bhi, const bf16* __restrict__ Blo,
    float* C, bf16* Chi, bf16* Clo,
    const float* bias_row, const float* bias_col,
    int Ktot, int ldc, long sA, long sB, long sC, float alpha)
{
    __shared__ bf16 sm[SM_TOT];
    const int tid  = threadIdx.x;
    const int lane = tid & 31;
    const int wid  = tid >> 5;
    const int wm   = (wid & 3) * 32;   // warp M offset in CTA tile
    const int wn   = (wid >> 2) * 32;  // warp N offset in CTA tile

    const long z  = blockIdx.z;
    const int m0  = blockIdx.y * BM;
    const int n0  = blockIdx.x * BN;
    const bf16* pAhi = Ahi + z * sA + (long)m0 * Ktot;
    const bf16* pAlo = Alo + z * sA + (long)m0 * Ktot;
    const bf16* pBhi = Bhi + z * sB + (long)n0 * Ktot;
    const bf16* pBlo = Blo + z * sB + (long)n0 * Ktot;

    float acc[2][4][4];
#pragma unroll
    for (int i = 0; i < 2; i++)
#pragma unroll
        for (int j = 0; j < 4; j++)
#pragma unroll
            for (int r = 0; r < 4; r++) acc[i][j][r] = 0.f;

    const u32 sb = smem_u32(sm);
    const int nch = Ktot / KC;

    for (int ch = 0; ch < nch; ch++) {
        __syncthreads();   // previous chunk's reads done before overwrite
        const long koff = (long)ch * KC;
        // A tiles: 128 rows x 32 bf16 = 512 uint4 per tile -> 2/thread
#pragma unroll
        for (int i = 0; i < 2; i++) {
            const int idx = i * 256 + tid;
            const int r = idx >> 2, c8 = (idx & 3) * 8;
            *(uint4*)(sm + SM_AHI + r * KSTR + c8) =
                *(const uint4*)(pAhi + (long)r * Ktot + koff + c8);
            *(uint4*)(sm + SM_ALO + r * KSTR + c8) =
                *(const uint4*)(pAlo + (long)r * Ktot + koff + c8);
        }
        // B tiles: 64 rows x 32 bf16 = 256 uint4 per tile -> 1/thread
        {
            const int r = tid >> 2, c8 = (tid & 3) * 8;
            *(uint4*)(sm + SM_BHI + r * KSTR + c8) =
                *(const uint4*)(pBhi + (long)r * Ktot + koff + c8);
            *(uint4*)(sm + SM_BLO + r * KSTR + c8) =
                *(const uint4*)(pBlo + (long)r * Ktot + koff + c8);
        }
        __syncthreads();

#pragma unroll
        for (int ks = 0; ks < KC / 16; ks++) {
            const int k16 = ks * 16;
            u32 ah[2][4], al[2][4], bh[4][2], bl[4][2];
            // A frags: x4 mats = (m0-7,k0-7),(m8-15,k0-7),(m0-7,k8-15),(m8-15,k8-15)
            const int arow = lane & 15;
            const int acol = k16 + (lane >> 4) * 8;
#pragma unroll
            for (int fm = 0; fm < 2; fm++) {
                const int off = (wm + fm * 16 + arow) * KSTR + acol;
                ldsm4(ah[fm][0], ah[fm][1], ah[fm][2], ah[fm][3], sb + (SM_AHI + off) * 2);
                ldsm4(al[fm][0], al[fm][1], al[fm][2], al[fm][3], sb + (SM_ALO + off) * 2);
            }
            // B frags: x4 mats = (n0-7,k0-7),(n0-7,k8-15),(n8-15,k0-7),(n8-15,k8-15)
            const int brow = (lane & 7) + ((lane >> 4) << 3);
            const int bcol = k16 + ((lane >> 3) & 1) * 8;
#pragma unroll
            for (int g = 0; g < 2; g++) {
                const int off = (wn + g * 16 + brow) * KSTR + bcol;
                u32 r0, r1, r2, r3;
                ldsm4(r0, r1, r2, r3, sb + (SM_BHI + off) * 2);
                bh[2 * g][0] = r0; bh[2 * g][1] = r1;
                bh[2 * g + 1][0] = r2; bh[2 * g + 1][1] = r3;
                ldsm4(r0, r1, r2, r3, sb + (SM_BLO + off) * 2);
                bl[2 * g][0] = r0; bl[2 * g][1] = r1;
                bl[2 * g + 1][0] = r2; bl[2 * g + 1][1] = r3;
            }
#pragma unroll
            for (int fm = 0; fm < 2; fm++)
#pragma unroll
                for (int nf = 0; nf < 4; nf++) {
                    mma16816(acc[fm][nf], ah[fm], bh[nf]);  // hi*hi
                    mma16816(acc[fm][nf], ah[fm], bl[nf]);  // hi*lo
                    mma16816(acc[fm][nf], al[fm], bh[nf]);  // lo*hi
                }
        }
    }

    // Epilogue: c0=(r,2c) c1=(r,2c+1) c2=(r+8,2c) c3=(r+8,2c+1); r=lane/4, c=lane%4
#pragma unroll
    for (int fm = 0; fm < 2; fm++) {
#pragma unroll
        for (int rr = 0; rr < 2; rr++) {
            const int m = m0 + wm + fm * 16 + (lane >> 2) + rr * 8;
            const float brw = bias_row ? bias_row[m] : 0.f;
#pragma unroll
            for (int nf = 0; nf < 4; nf++) {
                const int n = n0 + wn + nf * 8 + 2 * (lane & 3);
                float v0 = alpha * acc[fm][nf][rr * 2 + 0] + brw;
                float v1 = alpha * acc[fm][nf][rr * 2 + 1] + brw;
                if (bias_col) { v0 += bias_col[n]; v1 += bias_col[n + 1]; }
                const long ci = z * sC + (long)m * ldc + n;
                if (C) { C[ci] = v0; C[ci + 1] = v1; }
                if (Chi) {
                    const bf16 h0 = __float2bfloat16(v0);
                    const bf16 h1 = __float2bfloat16(v1);
                    Chi[ci] = h0; Chi[ci + 1] = h1;
                    Clo[ci]     = __float2bfloat16(v0 - __bfloat162float(h0));
                    Clo[ci + 1] = __float2bfloat16(v1 - __bfloat162float(h1));
                }
            }
        }
    }
}

// ---------------------------------------------------------------------------
// Conversions
// ---------------------------------------------------------------------------
__global__ void conv_hilo(const float* __restrict__ in, bf16* __restrict__ hi,
                          bf16* __restrict__ lo, long n) {
    const long i = (long)blockIdx.x * 256 + threadIdx.x;
    if (i < n) {
        const float v = in[i];
        const bf16 h = __float2bfloat16(v);
        hi[i] = h;
        lo[i] = __float2bfloat16(v - __bfloat162float(h));
    }
}

// x (b,c,n) fp32 -> (b,n,c) bf16 hi/lo
__global__ void conv_x_t(const float* __restrict__ x, bf16* __restrict__ hi,
                         bf16* __restrict__ lo) {
    const long i = (long)blockIdx.x * 256 + threadIdx.x;
    if (i < (long)BATCH * NTOK * CIND) {
        const int c = (int)(i & (CIND - 1));
        const long t = i >> 9;
        const int n = (int)(t & (NTOK - 1));
        const int b = (int)(t >> 10);
        const float v = x[(((long)b * CIND + c) << 10) | n];
        const bf16 h = __float2bfloat16(v);
        hi[i] = h;
        lo[i] = __float2bfloat16(v - __bfloat162float(h));
    }
}

// ---------------------------------------------------------------------------
// Masked softmax over rows of length SEQL; writes fp32 att (output) + hi/lo.
// ---------------------------------------------------------------------------
__global__ void __launch_bounds__(256) softmax_rows(
    const float* __restrict__ S, const unsigned char* __restrict__ mask,
    float* __restrict__ att, bf16* __restrict__ ahi, bf16* __restrict__ alo)
{
    __shared__ float red[256];
    const long row = blockIdx.x;
    const float* s = S + row * SEQL;
    const unsigned char* m = mask + row * SEQL;
    const int t = threadIdx.x;

    float v[4];
    float lm = -3.4e38f;
#pragma unroll
    for (int i = 0; i < 4; i++) {
        const int j = t + i * 256;
        v[i] = m[j] ? -1e9f : s[j];
        lm = fmaxf(lm, v[i]);
    }
    red[t] = lm;
    __syncthreads();
    for (int off = 128; off > 0; off >>= 1) {
        if (t < off) red[t] = fmaxf(red[t], red[t + off]);
        __syncthreads();
    }
    const float mx = red[0];
    __syncthreads();
    float ls = 0.f;
#pragma unroll
    for (int i = 0; i < 4; i++) {
        v[i] = __expf(v[i] - mx);
        ls += v[i];
    }
    red[t] = ls;
    __syncthreads();
    for (int off = 128; off > 0; off >>= 1) {
        if (t < off) red[t] += red[t + off];
        __syncthreads();
    }
    const float inv = 1.f / red[0];
#pragma unroll
    for (int i = 0; i < 4; i++) {
        const long j = row * SEQL + t + i * 256;
        const float p = v[i] * inv;
        att[j] = p;
        const bf16 h = __float2bfloat16(p);
        ahi[j] = h;
        alo[j] = __float2bfloat16(p - __bfloat162float(h));
    }
}

// ---------------------------------------------------------------------------
// Launch
// ---------------------------------------------------------------------------
extern "C" void kernel_launch(void* const* d_in, const int* in_sizes, int n_in,
                              void* d_out, int out_size)
{
    const float* x        = (const float*)d_in[0];
    const float* content  = (const float*)d_in[1];
    const unsigned char* pmask = (const unsigned char*)d_in[2];
    const float* W_in     = (const float*)d_in[3];
    const float* b_in     = (const float*)d_in[4];
    const float* Wq       = (const float*)d_in[5];
    const float* Wk       = (const float*)d_in[6];
    const float* Wv       = (const float*)d_in[7];
    const float* W_out    = (const float*)d_in[8];
    const float* b_out    = (const float*)d_in[9];

    float* out = (float*)d_out;                       // (8,512,32,32)
    float* att = out + (long)BATCH * CIND * NTOK;     // (8,1024,1024)

    bf16 *XThi, *XTlo, *CThi, *CTlo, *WIhi, *WIlo, *WQhi, *WQlo, *WKhi, *WKlo;
    bf16 *WVhi, *WVlo, *WOhi, *WOlo, *XPhi, *XPlo, *Qhi, *Qlo, *Khi, *Klo;
    bf16 *VThi, *VTlo, *AThi, *ATlo, *AOhi, *AOlo;
    float* Sp;
    cudaGetSymbolAddress((void**)&XThi, g_XThi); cudaGetSymbolAddress((void**)&XTlo, g_XTlo);
    cudaGetSymbolAddress((void**)&CThi, g_CThi); cudaGetSymbolAddress((void**)&CTlo, g_CTlo);
    cudaGetSymbolAddress((void**)&WIhi, g_WIhi); cudaGetSymbolAddress((void**)&WIlo, g_WIlo);
    cudaGetSymbolAddress((void**)&WQhi, g_WQhi); cudaGetSymbolAddress((void**)&WQlo, g_WQlo);
    cudaGetSymbolAddress((void**)&WKhi, g_WKhi); cudaGetSymbolAddress((void**)&WKlo, g_WKlo);
    cudaGetSymbolAddress((void**)&WVhi, g_WVhi); cudaGetSymbolAddress((void**)&WVlo, g_WVlo);
    cudaGetSymbolAddress((void**)&WOhi, g_WOhi); cudaGetSymbolAddress((void**)&WOlo, g_WOlo);
    cudaGetSymbolAddress((void**)&XPhi, g_XPhi); cudaGetSymbolAddress((void**)&XPlo, g_XPlo);
    cudaGetSymbolAddress((void**)&Qhi,  g_Qhi);  cudaGetSymbolAddress((void**)&Qlo,  g_Qlo);
    cudaGetSymbolAddress((void**)&Khi,  g_Khi);  cudaGetSymbolAddress((void**)&Klo,  g_Klo);
    cudaGetSymbolAddress((void**)&VThi, g_VThi); cudaGetSymbolAddress((void**)&VTlo, g_VTlo);
    cudaGetSymbolAddress((void**)&AThi, g_AThi); cudaGetSymbolAddress((void**)&ATlo, g_ATlo);
    cudaGetSymbolAddress((void**)&AOhi, g_AOhi); cudaGetSymbolAddress((void**)&AOlo, g_AOlo);
    cudaGetSymbolAddress((void**)&Sp,   g_S);

    // input conversions
    conv_x_t<<<(BATCH * NTOK * CIND + 255) / 256, 256>>>(x, XThi, XTlo);
    conv_hilo<<<(BATCH * SEQL * EMBD + 255) / 256, 256>>>(content, CThi, CTlo,
                                                          (long)BATCH * SEQL * EMBD);
    conv_hilo<<<(EMBD * CIND + 255) / 256, 256>>>(W_in, WIhi, WIlo, EMBD * CIND);
    conv_hilo<<<(EMBD * EMBD + 255) / 256, 256>>>(Wq, WQhi, WQlo, EMBD * EMBD);
    conv_hilo<<<(EMBD * EMBD + 255) / 256, 256>>>(Wk, WKhi, WKlo, EMBD * EMBD);
    conv_hilo<<<(EMBD * EMBD + 255) / 256, 256>>>(Wv, WVhi, WVlo, EMBD * EMBD);
    conv_hilo<<<(CIND * EMBD + 255) / 256, 256>>>(W_out, WOhi, WOlo, CIND * EMBD);

    const dim3 blk(256);
    const long LE = (long)NTOK * EMBD;   // per-batch activation stride (1M)

    // 1) proj_in: D[token][e] = XT[token][c] . WIN[e][c] + b_in[e]  -> XP hi/lo
    mma_gemm<<<dim3(EMBD / BN, NTOK / BM, BATCH), blk>>>(
        XThi, XTlo, WIhi, WIlo, nullptr, XPhi, XPlo, nullptr, b_in,
        CIND, EMBD, (long)NTOK * CIND, 0L, LE, 1.f);

    // 2) Q: D[token][e'] = XP . WQ^T  -> Q hi/lo
    mma_gemm<<<dim3(EMBD / BN, NTOK / BM, BATCH), blk>>>(
        XPhi, XPlo, WQhi, WQlo, nullptr, Qhi, Qlo, nullptr, nullptr,
        EMBD, EMBD, LE, 0L, LE, 1.f);

    // 3) K: D[s][e'] = content . WK^T  -> K hi/lo
    mma_gemm<<<dim3(EMBD / BN, SEQL / BM, BATCH), blk>>>(
        CThi, CTlo, WKhi, WKlo, nullptr, Khi, Klo, nullptr, nullptr,
        EMBD, EMBD, (long)SEQL * EMBD, 0L, LE, 1.f);

    // 4) V^T: D[d][s] = WV[d][e] . content[s][e]  -> VT hi/lo
    mma_gemm<<<dim3(SEQL / BN, EMBD / BM, BATCH), blk>>>(
        WVhi, WVlo, CThi, CTlo, nullptr, VThi, VTlo, nullptr, nullptr,
        EMBD, SEQL, 0L, (long)SEQL * EMBD, LE, 1.f);

    // 5) scores: D[i][j] = scale * Q[i][.] . K[j][.]  -> S fp32
    mma_gemm<<<dim3(SEQL / BN, NTOK / BM, BATCH), blk>>>(
        Qhi, Qlo, Khi, Klo, Sp, nullptr, nullptr, nullptr, nullptr,
        EMBD, SEQL, LE, LE, (long)NTOK * SEQL, 0.03125f);

    // 6) softmax (+ att output + hi/lo)
    softmax_rows<<<BATCH * NTOK, 256>>>(Sp, pmask, att, AThi, ATlo);

    // 7) att@V: D[i][d] = att[i][j] . VT[d][j]  -> AO hi/lo
    mma_gemm<<<dim3(EMBD / BN, NTOK / BM, BATCH), blk>>>(
        AThi, ATlo, VThi, VTlo, nullptr, AOhi, AOlo, nullptr, nullptr,
        SEQL, EMBD, (long)NTOK * SEQL, LE, LE, 1.f);

    // 8) proj_out: D[c][n] = WO[c][e] . AO[n][e] + b_out[c]  -> out fp32
    mma_gemm<<<dim3(NTOK / BN, CIND / BM, BATCH), blk>>>(
        WOhi, WOlo, AOhi, AOlo, out, nullptr, nullptr, b_out, nullptr,
        EMBD, NTOK, 0L, LE, (long)CIND * NTOK, 1.f);
}